// round 12
// baseline (speedup 1.0000x reference)
#include <cuda_runtime.h>
#include <cstdint>

// SSIM loss, separable Gaussian 11x11 on fields {s,d,s^2,d^2}, s=x+y, d=x-y.
// Staging-free horizontal (direct predicated GMEM reads), 44-slot AoS ring,
// vertical 8 rows/thread x 2 passes. Explicit u32 shared addressing (no IMAD
// on the fma pipe), reduced-op SSIM epilogue with imm-FFMA and rcp.approx.

namespace {
constexpr int WI = 512, HI = 512;
constexpr int SW = 64;              // strip width
constexpr int RW4 = 64;             // ring row stride in float4
constexpr int NSLOT = 44;
constexpr int RINGB = NSLOT * RW4 * 16;  // ring bytes = 45056
constexpr float C1c = 1e-4f;
constexpr float C2c = 9e-4f;
constexpr double NPIX = 25165824.0; // 32*3*512*512
constexpr unsigned NBLK = 8 * 8 * 96;
}

__device__ double g_accum;
__device__ unsigned g_done;

using u64 = unsigned long long;

__device__ __forceinline__ u64 pk(float a, float b) {
    union { float2 f; u64 u; } c; c.f.x = a; c.f.y = b; return c.u;
}
__device__ __forceinline__ void upk(float& a, float& b, u64 v) {
    union { float2 f; u64 u; } c; c.u = v; a = c.f.x; b = c.f.y;
}
__device__ __forceinline__ u64 ffma2(u64 a, u64 b, u64 c) {
    u64 d; asm("fma.rn.f32x2 %0, %1, %2, %3;" : "=l"(d) : "l"(a), "l"(b), "l"(c));
    return d;
}
__device__ __forceinline__ u64 fmul2(u64 a, u64 b) {
    u64 d; asm("mul.rn.f32x2 %0, %1, %2;" : "=l"(d) : "l"(a), "l"(b));
    return d;
}
__device__ __forceinline__ int SWZ4(int c) { return c ^ (((c) >> 3) & 7); }

__device__ __forceinline__ ulonglong2 lds128(uint32_t a) {
    ulonglong2 v;
    asm("ld.shared.v2.u64 {%0, %1}, [%2];" : "=l"(v.x), "=l"(v.y) : "r"(a));
    return v;
}
__device__ __forceinline__ void sts128(uint32_t a, u64 x, u64 y) {
    asm volatile("st.shared.v2.u64 [%0], {%1, %2};" :: "r"(a), "l"(x), "l"(y));
}

__global__ void __launch_bounds__(256, 4) ssim_main(const float* __restrict__ img1,
                                                    const float* __restrict__ img2,
                                                    float* __restrict__ out)
{
    __shared__ float4 Ring[NSLOT][RW4];  // {S,D,S2,D2} per px
    __shared__ float wsum[8];

    const float Wf[6] = {0.00102838f, 0.00759877f, 0.03600077f,
                         0.10936070f, 0.21300552f, 0.26601174f};
    u64 wp[6];
    #pragma unroll
    for (int i = 0; i < 6; i++) wp[i] = pk(Wf[i], Wf[i]);

    const int tid   = threadIdx.x;
    const int x0    = blockIdx.x * SW;
    const int segY  = blockIdx.y * 64;
    const int plane = blockIdx.z;
    const float* p1 = img1 + (size_t)plane * (size_t)(WI * HI);
    const float* p2 = img2 + (size_t)plane * (size_t)(WI * HI);

    uint32_t ringU;
    { uint32_t t;
      asm("{ .reg .u64 x; cvta.to.shared.u64 x, %1; cvt.u32.u64 %0, x; }"
          : "=r"(t) : "l"(&Ring[0][0])); ringU = t; }

    const int hrow = tid >> 4;           // 0..15
    const int hcg  = tid & 15;           // 0..15 (4 outputs each)
    const int vx   = tid & 63;
    const int vrg  = tid >> 6;           // 0..3

    // precomputed shared addresses (no IMAD in hot loops)
    const uint32_t hStBase = ringU + (uint32_t)(hrow << 10);       // + slotBase*1024 + swzOff
    uint32_t swzOff[4];
    #pragma unroll
    for (int o = 0; o < 4; o++) swzOff[o] = (uint32_t)(SWZ4(hcg * 4 + o) << 4);
    const uint32_t vLdBase = ringU + (uint32_t)(SWZ4(vx) << 4);
    const uint32_t vLim    = ringU + (uint32_t)RINGB;

    // column window validity (units fully in/out; offsets 2/4-px aligned)
    const int gbx = x0 - 8 + hcg * 4;
    const bool cin0 = (gbx + 2  >= 0) && (gbx + 4  <= WI);
    const bool cin1 = (gbx + 4  >= 0) && (gbx + 8  <= WI);
    const bool cin2 = (gbx + 8  >= 0) && (gbx + 12 <= WI);
    const bool cin3 = (gbx + 12 >= 0) && (gbx + 16 <= WI);
    const bool cin4 = (gbx + 16 >= 0) && (gbx + 18 <= WI);

    float acc = 0.f;

    // horizontal conv of global row ty -> ring (stBase = hStBase + slotBase*1024)
    auto hzg = [&](uint32_t stBase, int ty) {
        const bool rowIn = ((unsigned)ty < (unsigned)HI);
        const size_t ro = (size_t)(rowIn ? ty : 0) * WI;
        const float* rA = p1 + ro + gbx;
        const float* rB = p2 + ro + gbx;

        const float2 z2 = make_float2(0.f, 0.f);
        const float4 z4 = make_float4(0.f, 0.f, 0.f, 0.f);
        float2 a0 = (rowIn && cin0) ? *reinterpret_cast<const float2*>(rA + 2)  : z2;
        float2 b0 = (rowIn && cin0) ? *reinterpret_cast<const float2*>(rB + 2)  : z2;
        float4 a1 = (rowIn && cin1) ? *reinterpret_cast<const float4*>(rA + 4)  : z4;
        float4 b1 = (rowIn && cin1) ? *reinterpret_cast<const float4*>(rB + 4)  : z4;
        float4 a2 = (rowIn && cin2) ? *reinterpret_cast<const float4*>(rA + 8)  : z4;
        float4 b2 = (rowIn && cin2) ? *reinterpret_cast<const float4*>(rB + 8)  : z4;
        float4 a3 = (rowIn && cin3) ? *reinterpret_cast<const float4*>(rA + 12) : z4;
        float4 b3 = (rowIn && cin3) ? *reinterpret_cast<const float4*>(rB + 12) : z4;
        float2 a4 = (rowIn && cin4) ? *reinterpret_cast<const float2*>(rA + 16) : z2;
        float2 b4 = (rowIn && cin4) ? *reinterpret_cast<const float2*>(rB + 16) : z2;

        u64 aSD[4] = {0ull, 0ull, 0ull, 0ull};
        u64 aSQ[4] = {0ull, 0ull, 0ull, 0ull};

        auto tap = [&](int q, float a, float b) {   // q = window px index (3..16)
            const u64 sd = pk(a + b, a - b);
            const u64 sq = fmul2(sd, sd);
            #pragma unroll
            for (int o = 0; o < 4; o++) {
                const int t = q - 3 - o;
                if (t >= 0 && t <= 10) {
                    const int m = (t < 6) ? t : 10 - t;
                    aSD[o] = ffma2(sd, wp[m], aSD[o]);
                    aSQ[o] = ffma2(sq, wp[m], aSQ[o]);
                }
            }
        };

        tap(3,  a0.y, b0.y);
        tap(4,  a1.x, b1.x); tap(5,  a1.y, b1.y); tap(6,  a1.z, b1.z); tap(7,  a1.w, b1.w);
        tap(8,  a2.x, b2.x); tap(9,  a2.y, b2.y); tap(10, a2.z, b2.z); tap(11, a2.w, b2.w);
        tap(12, a3.x, b3.x); tap(13, a3.y, b3.y); tap(14, a3.z, b3.z); tap(15, a3.w, b3.w);
        tap(16, a4.x, b4.x);

        #pragma unroll
        for (int o = 0; o < 4; o++)
            sts128(stBase + swzOff[o], aSD[o], aSQ[o]);
    };

    // vertical: 8 output rows/thread over 18 ring slots, byte-address walk
    auto vert = [&](int m) {
        int s0 = m * 32 + vrg * 8;
        if (s0 >= NSLOT) s0 -= NSLOT;
        uint32_t addr = vLdBase + (uint32_t)(s0 << 10);
        u64 aSD[8], aSQ[8];
        #pragma unroll
        for (int o = 0; o < 8; o++) { aSD[o] = 0ull; aSQ[o] = 0ull; }
        #pragma unroll
        for (int r = 0; r < 18; r++) {
            ulonglong2 v = lds128(addr);
            addr += 1024u;
            if (addr >= vLim) addr -= (uint32_t)RINGB;
            #pragma unroll
            for (int o = 0; o < 8; o++) {
                const int t = r - o;
                if (t >= 0 && t <= 10) {
                    const int mm = (t < 6) ? t : 10 - t;
                    aSD[o] = ffma2(v.x, wp[mm], aSD[o]);
                    aSQ[o] = ffma2(v.y, wp[mm], aSQ[o]);
                }
            }
        }
        #pragma unroll
        for (int o = 0; o < 8; o++) {
            float P, Q, es, ed;
            upk(P, Q, fmul2(aSD[o], aSD[o]));        // (mu_s^2, mu_d^2)
            upk(es, ed, aSQ[o]);
            const float U  = P - Q;                  // 4*mu1*mu2
            const float V  = P + Q;                  // 2*(mu1^2+mu2^2)
            const float w1 = (es - ed) - U;          // 4*sigma12
            const float z1 = (es + ed) - V;          // 2*(sig1^2+sig2^2)
            const float numA = fmaf(0.5f, U,  C1c);  // 2*mu12 + C1
            const float numB = fmaf(0.5f, w1, C2c);  // 2*sigma12 + C2
            const float denA = fmaf(0.5f, V,  C1c);  // musum + C1
            const float denB = fmaf(0.5f, z1, C2c);  // sigsum + C2
            const float num = numA * numB;
            const float den = denA * denB;
            float rd; asm("rcp.approx.ftz.f32 %0, %1;" : "=f"(rd) : "f"(den));
            acc = fmaf(num, rd, acc);
        }
    };

    // ---- schedule (segment-local rows t = gy - segY; slot(t) = (t+5) mod 44) ----
    // Phase A: rows t = -5..38 (44 rows) -> slots 0..43
    hzg(hStBase,                 segY - 5 + hrow);
    hzg(hStBase + (16u << 10),   segY + 11 + hrow);
    if (hrow < 12) hzg(hStBase + (32u << 10), segY + 27 + hrow);
    __syncthreads();

    vert(0);                     // output rows 0..31, reads slots 0..41
    __syncthreads();             // vert(0) reads done before slot reuse

    // Phase B: rows t = 39..68 (30 rows) -> slots 0..29
    hzg(hStBase,                 segY + 39 + hrow);
    if (hrow < 14) hzg(hStBase + (16u << 10), segY + 55 + hrow);
    __syncthreads();

    vert(1);                     // output rows 32..63, reads slots 32..43, 0..29

    // ---- block reduction -> one double atomic per block ----
    #pragma unroll
    for (int off = 16; off > 0; off >>= 1)
        acc += __shfl_down_sync(0xffffffffu, acc, off);
    if ((tid & 31) == 0) wsum[tid >> 5] = acc;
    __syncthreads();
    if (tid == 0) {
        float s = 0.f;
        #pragma unroll
        for (int i = 0; i < 8; i++) s += wsum[i];
        atomicAdd(&g_accum, (double)s);
        __threadfence();
        unsigned t = atomicAdd(&g_done, 1u);
        if (t == NBLK - 1) {
            double tot = atomicAdd(&g_accum, 0.0);
            out[0] = (float)(1.0 - tot * (1.0 / NPIX));
            g_accum = 0.0;
            g_done  = 0u;
        }
    }
}

extern "C" void kernel_launch(void* const* d_in, const int* in_sizes, int n_in,
                              void* d_out, int out_size) {
    (void)in_sizes; (void)n_in; (void)out_size;
    const float* img1 = (const float*)d_in[0];
    const float* img2 = (const float*)d_in[1];
    ssim_main<<<dim3(WI / SW, HI / 64, 96), 256>>>(img1, img2, (float*)d_out);
}

// round 13
// speedup vs baseline: 1.0126x; 1.0126x over previous
#include <cuda_runtime.h>
#include <cstdint>

// SSIM loss, separable Gaussian 11x11 on fields {s,d,s^2,d^2}, s=x+y, d=x-y.
// Staging-free horizontal at 8 outputs/thread (18-px window, 32 rows/call),
// 44-slot AoS ring, vertical 8 rows/thread x 2 passes. 3 block barriers.

namespace {
constexpr int WI = 512, HI = 512;
constexpr int SW = 64;              // strip width
constexpr int RW4 = 64;             // ring row stride in float4
constexpr int NSLOT = 44;
constexpr float C1c = 1e-4f;
constexpr float C2c = 9e-4f;
constexpr double NPIX = 25165824.0; // 32*3*512*512
constexpr unsigned NBLK = 8 * 8 * 96;
}

__device__ double g_accum;
__device__ unsigned g_done;

using u64 = unsigned long long;

__device__ __forceinline__ u64 pk(float a, float b) {
    union { float2 f; u64 u; } c; c.f.x = a; c.f.y = b; return c.u;
}
__device__ __forceinline__ void upk(float& a, float& b, u64 v) {
    union { float2 f; u64 u; } c; c.u = v; a = c.f.x; b = c.f.y;
}
__device__ __forceinline__ u64 ffma2(u64 a, u64 b, u64 c) {
    u64 d; asm("fma.rn.f32x2 %0, %1, %2, %3;" : "=l"(d) : "l"(a), "l"(b), "l"(c));
    return d;
}
__device__ __forceinline__ u64 fmul2(u64 a, u64 b) {
    u64 d; asm("mul.rn.f32x2 %0, %1, %2;" : "=l"(d) : "l"(a), "l"(b));
    return d;
}
__device__ __forceinline__ int SWZ4(int c) { return c ^ (((c) >> 3) & 7); }

__global__ void __launch_bounds__(256, 4) ssim_main(const float* __restrict__ img1,
                                                    const float* __restrict__ img2,
                                                    float* __restrict__ out)
{
    __shared__ float4 Ring[NSLOT][RW4];  // {S,D,S2,D2} per px
    __shared__ float wsum[8];

    const float Wf[6] = {0.00102838f, 0.00759877f, 0.03600077f,
                         0.10936070f, 0.21300552f, 0.26601174f};
    u64 wp[6];
    #pragma unroll
    for (int i = 0; i < 6; i++) wp[i] = pk(Wf[i], Wf[i]);

    const int tid   = threadIdx.x;
    const int x0    = blockIdx.x * SW;
    const int segY  = blockIdx.y * 64;
    const int plane = blockIdx.z;
    const float* p1 = img1 + (size_t)plane * (size_t)(WI * HI);
    const float* p2 = img2 + (size_t)plane * (size_t)(WI * HI);

    const int h8row = tid >> 3;          // 0..31 (row within a 32-row call)
    const int h8cg  = tid & 7;           // 0..7  (8 outputs each)
    const int vx    = tid & 63;
    const int vrg   = tid >> 6;          // 0..3
    const int vswz  = SWZ4(vx);
    const float4* ringp = &Ring[0][0];

    // horizontal window: outputs at cols h8cg*8..+7; window rel px 3..20
    const int gbx8 = x0 - 8 + h8cg * 8;
    const bool cin0 = (gbx8 + 2  >= 0) && (gbx8 + 4  <= WI);  // .64  px 2-3
    const bool cin1 = (gbx8 + 4  >= 0) && (gbx8 + 8  <= WI);  // .128 px 4-7
    const bool cin2 = (gbx8 + 8  >= 0) && (gbx8 + 12 <= WI);  // .128 px 8-11
    const bool cin3 = (gbx8 + 12 >= 0) && (gbx8 + 16 <= WI);  // .128 px 12-15
    const bool cin4 = (gbx8 + 16 >= 0) && (gbx8 + 20 <= WI);  // .128 px 16-19
    const bool cin5 = (gbx8 + 20 >= 0) && (gbx8 + 22 <= WI);  // .64  px 20-21

    float acc = 0.f;

    // horizontal conv of global row ty -> ring slot, 8 outputs
    auto h8 = [&](int slot, int ty) {
        const bool rowIn = ((unsigned)ty < (unsigned)HI);
        const size_t ro = (size_t)(rowIn ? ty : 0) * WI;
        const float* rA = p1 + ro + gbx8;
        const float* rB = p2 + ro + gbx8;

        const float2 z2 = make_float2(0.f, 0.f);
        const float4 z4 = make_float4(0.f, 0.f, 0.f, 0.f);
        float2 a0 = (rowIn && cin0) ? *reinterpret_cast<const float2*>(rA + 2)  : z2;
        float2 b0 = (rowIn && cin0) ? *reinterpret_cast<const float2*>(rB + 2)  : z2;
        float4 a1 = (rowIn && cin1) ? *reinterpret_cast<const float4*>(rA + 4)  : z4;
        float4 b1 = (rowIn && cin1) ? *reinterpret_cast<const float4*>(rB + 4)  : z4;
        float4 a2 = (rowIn && cin2) ? *reinterpret_cast<const float4*>(rA + 8)  : z4;
        float4 b2 = (rowIn && cin2) ? *reinterpret_cast<const float4*>(rB + 8)  : z4;
        float4 a3 = (rowIn && cin3) ? *reinterpret_cast<const float4*>(rA + 12) : z4;
        float4 b3 = (rowIn && cin3) ? *reinterpret_cast<const float4*>(rB + 12) : z4;
        float4 a4 = (rowIn && cin4) ? *reinterpret_cast<const float4*>(rA + 16) : z4;
        float4 b4 = (rowIn && cin4) ? *reinterpret_cast<const float4*>(rB + 16) : z4;
        float2 a5 = (rowIn && cin5) ? *reinterpret_cast<const float2*>(rA + 20) : z2;
        float2 b5 = (rowIn && cin5) ? *reinterpret_cast<const float2*>(rB + 20) : z2;

        u64 aSD[8], aSQ[8];
        #pragma unroll
        for (int o = 0; o < 8; o++) { aSD[o] = 0ull; aSQ[o] = 0ull; }

        auto tap = [&](int q, float a, float b) {   // q = window px index (3..20)
            const u64 sd = pk(a + b, a - b);
            const u64 sq = fmul2(sd, sd);
            #pragma unroll
            for (int o = 0; o < 8; o++) {
                const int t = q - 3 - o;
                if (t >= 0 && t <= 10) {
                    const int m = (t < 6) ? t : 10 - t;
                    aSD[o] = ffma2(sd, wp[m], aSD[o]);
                    aSQ[o] = ffma2(sq, wp[m], aSQ[o]);
                }
            }
        };

        tap(3,  a0.y, b0.y);
        tap(4,  a1.x, b1.x); tap(5,  a1.y, b1.y); tap(6,  a1.z, b1.z); tap(7,  a1.w, b1.w);
        tap(8,  a2.x, b2.x); tap(9,  a2.y, b2.y); tap(10, a2.z, b2.z); tap(11, a2.w, b2.w);
        tap(12, a3.x, b3.x); tap(13, a3.y, b3.y); tap(14, a3.z, b3.z); tap(15, a3.w, b3.w);
        tap(16, a4.x, b4.x); tap(17, a4.y, b4.y); tap(18, a4.z, b4.z); tap(19, a4.w, b4.w);
        tap(20, a5.x, b5.x);

        #pragma unroll
        for (int o = 0; o < 8; o++) {
            ulonglong2 st; st.x = aSD[o]; st.y = aSQ[o];
            *reinterpret_cast<ulonglong2*>(&Ring[slot][SWZ4(h8cg * 8 + o)]) = st;
        }
    };

    // vertical: 8 output rows/thread over 18 ring slots, runtime slot walk
    auto vert = [&](int m) {
        int s = m * 32 + vrg * 8;
        if (s >= NSLOT) s -= NSLOT;
        u64 aSD[8], aSQ[8];
        #pragma unroll
        for (int o = 0; o < 8; o++) { aSD[o] = 0ull; aSQ[o] = 0ull; }
        #pragma unroll
        for (int r = 0; r < 18; r++) {
            ulonglong2 v = *reinterpret_cast<const ulonglong2*>(ringp + s * RW4 + vswz);
            s++; if (s == NSLOT) s = 0;
            #pragma unroll
            for (int o = 0; o < 8; o++) {
                const int t = r - o;
                if (t >= 0 && t <= 10) {
                    const int mm = (t < 6) ? t : 10 - t;
                    aSD[o] = ffma2(v.x, wp[mm], aSD[o]);
                    aSQ[o] = ffma2(v.y, wp[mm], aSQ[o]);
                }
            }
        }
        #pragma unroll
        for (int o = 0; o < 8; o++) {
            float mus_sq, mud_sq, es, ed;
            upk(mus_sq, mud_sq, fmul2(aSD[o], aSD[o]));
            upk(es, ed, aSQ[o]);
            const float mu12  = 0.25f * (mus_sq - mud_sq);   // mu1*mu2
            const float musum = 0.5f  * (mus_sq + mud_sq);   // mu1^2+mu2^2
            const float cross = 0.25f * (es - ed);           // conv(x*y)
            const float sqsum = 0.5f  * (es + ed);           // conv(x^2)+conv(y^2)
            const float sigma12 = cross - mu12;
            const float sigsum  = sqsum - musum;
            const float num = (2.f * mu12 + C1c) * (2.f * sigma12 + C2c);
            const float den = (musum + C1c) * (sigsum + C2c);
            acc += __fdividef(num, den);
        }
    };

    // ---- schedule (segment-local rows t = gy - segY; slot(t) = (t+5) mod 44) ----
    // Phase A: rows t = -5..38 (44 rows) -> slots 0..43
    h8(h8row, segY - 5 + h8row);                       // t -5..26 -> slots 0..31
    if (h8row < 12) h8(32 + h8row, segY + 27 + h8row); // t 27..38 -> slots 32..43
    __syncthreads();

    vert(0);                     // output rows 0..31, reads slots 0..41
    __syncthreads();             // vert(0) reads done before slot reuse

    // Phase B: rows t = 39..68 (30 rows) -> slots 0..29
    if (h8row < 30) h8(h8row, segY + 39 + h8row);
    __syncthreads();

    vert(1);                     // output rows 32..63, reads slots 32..43, 0..29

    // ---- block reduction -> one double atomic per block ----
    #pragma unroll
    for (int off = 16; off > 0; off >>= 1)
        acc += __shfl_down_sync(0xffffffffu, acc, off);
    if ((tid & 31) == 0) wsum[tid >> 5] = acc;
    __syncthreads();
    if (tid == 0) {
        float s = 0.f;
        #pragma unroll
        for (int i = 0; i < 8; i++) s += wsum[i];
        atomicAdd(&g_accum, (double)s);
        __threadfence();
        unsigned t = atomicAdd(&g_done, 1u);
        if (t == NBLK - 1) {
            double tot = atomicAdd(&g_accum, 0.0);
            out[0] = (float)(1.0 - tot * (1.0 / NPIX));
            g_accum = 0.0;
            g_done  = 0u;
        }
    }
}

extern "C" void kernel_launch(void* const* d_in, const int* in_sizes, int n_in,
                              void* d_out, int out_size) {
    (void)in_sizes; (void)n_in; (void)out_size;
    const float* img1 = (const float*)d_in[0];
    const float* img2 = (const float*)d_in[1];
    ssim_main<<<dim3(WI / SW, HI / 64, 96), 256>>>(img1, img2, (float*)d_out);
}